// round 1
// baseline (speedup 1.0000x reference)
#include <cuda_runtime.h>

#define TT 3072
#define DD 1024
#define NH 16
#define HX 64   // "head dim" X = 64

// Permuted per-head Q/K/V scratch: layout [h][t2][x], h-major.
__device__ __align__(16) float g_qp[TT * DD];
__device__ __align__(16) float g_kp[TT * DD];
__device__ __align__(16) float g_vp[TT * DD];

// ---------------------------------------------------------------------------
// Kernel 1: fused QKV projection  y = x @ W^T + b  with permuted scatter store
// Grid: (24 n-tiles over [Q|K|V], 24 t-tiles), 256 threads, 128x128 tile.
// ---------------------------------------------------------------------------
__global__ __launch_bounds__(256, 2)
void qkv_proj_kernel(const float* __restrict__ xin,
                     const float* __restrict__ wq, const float* __restrict__ bq,
                     const float* __restrict__ wk, const float* __restrict__ bk,
                     const float* __restrict__ wv, const float* __restrict__ bv)
{
    extern __shared__ float sm[];
    float (*s_x)[65] = (float (*)[65])(sm);
    float (*s_w)[65] = (float (*)[65])(sm + 128 * 65);

    const int tid = threadIdx.x;
    const int ty  = tid >> 4;
    const int tx  = tid & 15;
    const int t0  = blockIdx.y * 128;
    const int bn  = blockIdx.x;          // 0..23
    const int mat = bn >> 3;             // 0=Q 1=K 2=V
    const int col0 = (bn & 7) << 7;      // column within the 1024-wide matrix

    const float* W;
    const float* bias;
    float* dst;
    if (mat == 0)      { W = wq; bias = bq; dst = g_qp; }
    else if (mat == 1) { W = wk; bias = bk; dst = g_kp; }
    else               { W = wv; bias = bv; dst = g_vp; }

    float acc[8][8];
    #pragma unroll
    for (int r = 0; r < 8; r++)
        #pragma unroll
        for (int c = 0; c < 8; c++) acc[r][c] = 0.f;

    for (int k0 = 0; k0 < DD; k0 += 64) {
        // Load 128x64 tiles of x and W (both K-major, NT gemm) into smem.
        #pragma unroll
        for (int it = 0; it < 8; it++) {
            int idx = tid + it * 256;        // 2048 float4 per tile
            int row = idx >> 4;
            int c4  = (idx & 15) << 2;
            float4 vx = *(const float4*)(xin + (t0 + row) * DD + k0 + c4);
            s_x[row][c4 + 0] = vx.x; s_x[row][c4 + 1] = vx.y;
            s_x[row][c4 + 2] = vx.z; s_x[row][c4 + 3] = vx.w;
            float4 vw = *(const float4*)(W + (col0 + row) * DD + k0 + c4);
            s_w[row][c4 + 0] = vw.x; s_w[row][c4 + 1] = vw.y;
            s_w[row][c4 + 2] = vw.z; s_w[row][c4 + 3] = vw.w;
        }
        __syncthreads();

        #pragma unroll 8
        for (int kk = 0; kk < 64; kk++) {
            float a[8], b[8];
            #pragma unroll
            for (int r = 0; r < 8; r++) a[r] = s_x[ty * 8 + r][kk];
            #pragma unroll
            for (int c = 0; c < 8; c++) b[c] = s_w[tx * 8 + c][kk];
            #pragma unroll
            for (int r = 0; r < 8; r++)
                #pragma unroll
                for (int c = 0; c < 8; c++)
                    acc[r][c] += a[r] * b[c];
        }
        __syncthreads();
    }

    // Epilogue: bias + permuted scatter into [h][t2][x].
    // (t, col) -> x = t/48, e = (t%48)*1024 + col, t2 = e>>4, h = e&15
    #pragma unroll
    for (int r = 0; r < 8; r++) {
        int t    = t0 + ty * 8 + r;
        int xx   = t / 48;
        int toff = t - xx * 48;
        #pragma unroll
        for (int c = 0; c < 8; c++) {
            int nn = col0 + tx * 8 + c;
            float v = acc[r][c] + bias[nn];
            int e  = toff * 1024 + nn;
            int hh = e & 15;
            int ii = e >> 4;
            dst[(hh * TT + ii) * HX + xx] = v;
        }
    }
}

// ---------------------------------------------------------------------------
// Kernel 2: flash attention per (head, 128-query tile), fused epilogue
//   out[t2][x*16+h] = gamma * O[t2][x] + x_in[t2][x*16+h]
// Grid: (24 q-tiles, 16 heads), 256 threads.
// ---------------------------------------------------------------------------
__global__ __launch_bounds__(256, 1)
void attn_kernel(const float* __restrict__ xin,
                 const float* __restrict__ gamma_p,
                 float* __restrict__ out)
{
    extern __shared__ float sm[];
    float (*s_q)[65]  = (float (*)[65])(sm);                 // 128 x 64 Q tile
    float (*s_v)[65]  = (float (*)[65])(sm + 128 * 65);      // 128 x 64 V tile
    float (*s_k)[65]  = (float (*)[65])(sm + 2 * 128 * 65);  // K tile (union w/ P)
    float (*s_p)[129] = (float (*)[129])(sm + 2 * 128 * 65); // P tile 128x128

    const int tid = threadIdx.x;
    const int ty  = tid >> 4;
    const int tx  = tid & 15;
    const int h   = blockIdx.y;
    const int i0  = blockIdx.x * 128;

    const float* Qh = g_qp + h * TT * HX;
    const float* Kh = g_kp + h * TT * HX;
    const float* Vh = g_vp + h * TT * HX;

    // Load Q tile (128 x 64)
    #pragma unroll
    for (int it = 0; it < 8; it++) {
        int idx = tid + it * 256;
        int row = idx >> 4;
        int c4  = (idx & 15) << 2;
        float4 v = *(const float4*)(Qh + (i0 + row) * HX + c4);
        s_q[row][c4 + 0] = v.x; s_q[row][c4 + 1] = v.y;
        s_q[row][c4 + 2] = v.z; s_q[row][c4 + 3] = v.w;
    }

    float o[8][4];
    float mrow[8], lrow[8];
    #pragma unroll
    for (int r = 0; r < 8; r++) {
        mrow[r] = -1e30f;
        lrow[r] = 0.f;
        #pragma unroll
        for (int cc = 0; cc < 4; cc++) o[r][cc] = 0.f;
    }

    for (int j0 = 0; j0 < TT; j0 += 128) {
        // Load K and V tiles (each 128 x 64)
        #pragma unroll
        for (int it = 0; it < 8; it++) {
            int idx = tid + it * 256;
            int row = idx >> 4;
            int c4  = (idx & 15) << 2;
            float4 vk = *(const float4*)(Kh + (j0 + row) * HX + c4);
            s_k[row][c4 + 0] = vk.x; s_k[row][c4 + 1] = vk.y;
            s_k[row][c4 + 2] = vk.z; s_k[row][c4 + 3] = vk.w;
            float4 vv = *(const float4*)(Vh + (j0 + row) * HX + c4);
            s_v[row][c4 + 0] = vv.x; s_v[row][c4 + 1] = vv.y;
            s_v[row][c4 + 2] = vv.z; s_v[row][c4 + 3] = vv.w;
        }
        __syncthreads();

        // S = Q K^T  (128x128, k=64), 8x8 per thread
        float s[8][8];
        #pragma unroll
        for (int r = 0; r < 8; r++)
            #pragma unroll
            for (int c = 0; c < 8; c++) s[r][c] = 0.f;

        #pragma unroll 8
        for (int kk = 0; kk < 64; kk++) {
            float a[8], b[8];
            #pragma unroll
            for (int r = 0; r < 8; r++) a[r] = s_q[ty * 8 + r][kk];
            #pragma unroll
            for (int c = 0; c < 8; c++) b[c] = s_k[tx * 8 + c][kk];
            #pragma unroll
            for (int r = 0; r < 8; r++)
                #pragma unroll
                for (int c = 0; c < 8; c++)
                    s[r][c] += a[r] * b[c];
        }
        __syncthreads();  // everyone done reading s_k before s_p overwrites it

        // Online softmax (row stats shared by the 16 tx-threads via shuffles)
        float scale[8];
        #pragma unroll
        for (int r = 0; r < 8; r++) {
            float mx = s[r][0];
            #pragma unroll
            for (int c = 1; c < 8; c++) mx = fmaxf(mx, s[r][c]);
            #pragma unroll
            for (int off = 1; off < 16; off <<= 1)
                mx = fmaxf(mx, __shfl_xor_sync(0xffffffffu, mx, off));
            float mnew = fmaxf(mrow[r], mx);
            scale[r] = __expf(mrow[r] - mnew);
            float rs = 0.f;
            #pragma unroll
            for (int c = 0; c < 8; c++) {
                float p = __expf(s[r][c] - mnew);
                s[r][c] = p;
                rs += p;
            }
            #pragma unroll
            for (int off = 1; off < 16; off <<= 1)
                rs += __shfl_xor_sync(0xffffffffu, rs, off);
            lrow[r] = lrow[r] * scale[r] + rs;
            mrow[r] = mnew;
        }
        #pragma unroll
        for (int r = 0; r < 8; r++)
            #pragma unroll
            for (int cc = 0; cc < 4; cc++)
                o[r][cc] *= scale[r];

        // P -> smem
        #pragma unroll
        for (int r = 0; r < 8; r++)
            #pragma unroll
            for (int c = 0; c < 8; c++)
                s_p[ty * 8 + r][tx * 8 + c] = s[r][c];
        __syncthreads();

        // O += P @ V  (128x64, k=128), 8x4 per thread
        #pragma unroll 8
        for (int j = 0; j < 128; j++) {
            float a[8], b[4];
            #pragma unroll
            for (int r = 0; r < 8; r++) a[r] = s_p[ty * 8 + r][j];
            #pragma unroll
            for (int cc = 0; cc < 4; cc++) b[cc] = s_v[j][tx * 4 + cc];
            #pragma unroll
            for (int r = 0; r < 8; r++)
                #pragma unroll
                for (int cc = 0; cc < 4; cc++)
                    o[r][cc] += a[r] * b[cc];
        }
        __syncthreads();  // before next iteration's K/V loads
    }

    // Epilogue: normalize, gamma * O + residual, permuted store
    const float gma = *gamma_p;
    #pragma unroll
    for (int r = 0; r < 8; r++) {
        float inv = 1.0f / lrow[r];
        int row = i0 + ty * 8 + r;
        #pragma unroll
        for (int cc = 0; cc < 4; cc++) {
            int xcol = tx * 4 + cc;              // 0..63
            int idx  = row * DD + xcol * 16 + h;
            out[idx] = gma * (o[r][cc] * inv) + xin[idx];
        }
    }
}

// ---------------------------------------------------------------------------
extern "C" void kernel_launch(void* const* d_in, const int* in_sizes, int n_in,
                              void* d_out, int out_size)
{
    const float* xin = (const float*)d_in[0];
    const float* wq  = (const float*)d_in[1];
    const float* bq  = (const float*)d_in[2];
    const float* wk  = (const float*)d_in[3];
    const float* bk  = (const float*)d_in[4];
    const float* wv  = (const float*)d_in[5];
    const float* bv  = (const float*)d_in[6];
    const float* gm  = (const float*)d_in[7];
    float* out = (float*)d_out;

    const int smem_gemm = 2 * 128 * 65 * 4;                  // 66560 B
    const int smem_attn = (2 * 128 * 65 + 128 * 129) * 4;    // 132608 B
    cudaFuncSetAttribute(qkv_proj_kernel,
                         cudaFuncAttributeMaxDynamicSharedMemorySize, smem_gemm);
    cudaFuncSetAttribute(attn_kernel,
                         cudaFuncAttributeMaxDynamicSharedMemorySize, smem_attn);

    dim3 blk(256);
    qkv_proj_kernel<<<dim3(24, 24), blk, smem_gemm>>>(xin, wq, bq, wk, bk, wv, bv);
    attn_kernel<<<dim3(24, NH), blk, smem_attn>>>(xin, gm, out);
}

// round 4
// speedup vs baseline: 2.1980x; 2.1980x over previous
#include <cuda_runtime.h>
#include <cuda_bf16.h>
#include <cstdint>

#define TT 3072
#define DD 1024
#define NH 16
#define HX 64

// ---------------------------------------------------------------------------
// Global scratch
// ---------------------------------------------------------------------------
__device__ __align__(16) __nv_bfloat16 g_xhi[TT * DD], g_xlo[TT * DD];
__device__ __align__(16) __nv_bfloat16 g_whi[3 * DD * DD], g_wlo[3 * DD * DD];
// packed (hi | lo<<16) bf16 pairs
__device__ __align__(16) uint32_t g_q[TT * DD];   // [h][t][x]
__device__ __align__(16) uint32_t g_k[TT * DD];   // [h][j][x]
__device__ __align__(16) uint32_t g_vt[TT * DD];  // [h][x][j]  (pre-transposed)

// ---------------------------------------------------------------------------
// helpers
// ---------------------------------------------------------------------------
__device__ __forceinline__ uint32_t smem_u32(const void* p) {
    uint32_t a;
    asm("{ .reg .u64 t; cvta.to.shared.u64 t, %1; cvt.u32.u64 %0, t; }"
        : "=r"(a) : "l"(p));
    return a;
}
__device__ __forceinline__ void ldsm4(uint32_t& r0, uint32_t& r1,
                                      uint32_t& r2, uint32_t& r3, uint32_t a) {
    asm volatile("ldmatrix.sync.aligned.m8n8.x4.shared.b16 {%0,%1,%2,%3}, [%4];"
                 : "=r"(r0), "=r"(r1), "=r"(r2), "=r"(r3) : "r"(a));
}
__device__ __forceinline__ void mma16816(float* c, const uint32_t* a,
                                         uint32_t b0, uint32_t b1) {
    asm volatile("mma.sync.aligned.m16n8k16.row.col.f32.bf16.bf16.f32 "
                 "{%0,%1,%2,%3}, {%4,%5,%6,%7}, {%8,%9}, {%0,%1,%2,%3};"
                 : "+f"(c[0]), "+f"(c[1]), "+f"(c[2]), "+f"(c[3])
                 : "r"(a[0]), "r"(a[1]), "r"(a[2]), "r"(a[3]), "r"(b0), "r"(b1));
}
__device__ __forceinline__ void split_pack(float a, float b,
                                           uint32_t& hi, uint32_t& lo) {
    __nv_bfloat16 ha = __float2bfloat16(a), hb = __float2bfloat16(b);
    __nv_bfloat16 la = __float2bfloat16(a - __bfloat162float(ha));
    __nv_bfloat16 lb = __float2bfloat16(b - __bfloat162float(hb));
    hi = (uint32_t)__bfloat16_as_ushort(ha) |
         ((uint32_t)__bfloat16_as_ushort(hb) << 16);
    lo = (uint32_t)__bfloat16_as_ushort(la) |
         ((uint32_t)__bfloat16_as_ushort(lb) << 16);
}

// ---------------------------------------------------------------------------
// Kernel 0: convert x and W to bf16 hi/lo once
// ---------------------------------------------------------------------------
__global__ __launch_bounds__(256)
void prep_kernel(const float* __restrict__ x, const float* __restrict__ wq,
                 const float* __restrict__ wk, const float* __restrict__ wv)
{
    const int NX4 = TT * DD / 4;   // 786432
    const int NW4 = DD * DD / 4;   // 262144
    int base = blockIdx.x * blockDim.x + threadIdx.x;
    #pragma unroll
    for (int it = 0; it < 2; it++) {
        int idx = base + it * 786432;
        const float* src;
        __nv_bfloat16 *dhi, *dlo;
        int off;
        if (idx < NX4) { src = x; dhi = g_xhi; dlo = g_xlo; off = idx * 4; }
        else {
            int j = idx - NX4;
            int w = j / NW4;
            int o = j - w * NW4;
            src = (w == 0) ? wq : ((w == 1) ? wk : wv);
            dhi = g_whi + w * DD * DD;
            dlo = g_wlo + w * DD * DD;
            off = o * 4;
        }
        float4 v = *(const float4*)(src + off);
        float f[4] = {v.x, v.y, v.z, v.w};
        uint32_t h01, l01, h23, l23;
        split_pack(f[0], f[1], h01, l01);
        split_pack(f[2], f[3], h23, l23);
        *(uint2*)(dhi + off) = make_uint2(h01, h23);
        *(uint2*)(dlo + off) = make_uint2(l01, l23);
    }
}

// ---------------------------------------------------------------------------
// Kernel 1: QKV projection via mma.sync, permuted packed scatter epilogue
// Grid (24 n-tiles over [Q|K|V], 24 t-tiles), 256 threads, 128x128 tile.
// smem: A_hi/A_lo/B_hi/B_lo each 128 rows x 40 u16 (80B stride) = 40960 B
// ---------------------------------------------------------------------------
#define GAHI 0
#define GALO 10240
#define GBHI 20480
#define GBLO 30720
#define SMEM_G 40960

__global__ __launch_bounds__(256, 1)
void qkv_mma_kernel(const float* __restrict__ bq, const float* __restrict__ bk,
                    const float* __restrict__ bv)
{
    extern __shared__ char sm[];
    const uint32_t sb = smem_u32(sm);
    const int tid = threadIdx.x;
    const int lane = tid & 31;
    const int wid = tid >> 5;
    const int wm = wid & 1;        // 2 m-tiles of 64
    const int wn = wid >> 1;       // 4 n-tiles of 32
    const int t0 = blockIdx.y * 128;
    const int bn = blockIdx.x;
    const int mat = bn >> 3;
    const int col0 = (bn & 7) << 7;
    const float* bias = (mat == 0) ? bq : ((mat == 1) ? bk : bv);
    const __nv_bfloat16* GBh = g_whi + mat * DD * DD;
    const __nv_bfloat16* GBl = g_wlo + mat * DD * DD;

    const int lrow = lane & 15;
    const int lk = (lane >> 4) << 3;

    float c[4][4][4];
    #pragma unroll
    for (int i = 0; i < 4; i++)
        #pragma unroll
        for (int j = 0; j < 4; j++)
            #pragma unroll
            for (int e = 0; e < 4; e++) c[i][j][e] = 0.f;

    for (int k0 = 0; k0 < DD; k0 += 32) {
        // 512 chunks of 8 bf16 (16 B = uint4): 128 rows x 4 chunks per buffer
        #pragma unroll
        for (int i = 0; i < 2; i++) {
            int idx = tid + i * 256;
            int row = idx >> 2;
            int c8 = (idx & 3) << 3;              // element offset, 8 bf16 = 16 B
            int so = row * 80 + c8 * 2;           // byte offset in smem
            *(uint4*)(sm + GAHI + so) = *(const uint4*)(g_xhi + (t0 + row) * DD + k0 + c8);
            *(uint4*)(sm + GALO + so) = *(const uint4*)(g_xlo + (t0 + row) * DD + k0 + c8);
            *(uint4*)(sm + GBHI + so) = *(const uint4*)(GBh + (col0 + row) * DD + k0 + c8);
            *(uint4*)(sm + GBLO + so) = *(const uint4*)(GBl + (col0 + row) * DD + k0 + c8);
        }
        __syncthreads();

        #pragma unroll
        for (int ks = 0; ks < 2; ks++) {
            int kb = ks << 4;
            uint32_t ah[4][4], al[4][4];
            #pragma unroll
            for (int mf = 0; mf < 4; mf++) {
                uint32_t ad = sb + GAHI +
                    ((wm * 64 + mf * 16 + lrow) * 40 + kb + lk) * 2;
                ldsm4(ah[mf][0], ah[mf][1], ah[mf][2], ah[mf][3], ad);
                ldsm4(al[mf][0], al[mf][1], al[mf][2], al[mf][3],
                      ad + (GALO - GAHI));
            }
            uint32_t bh[4][2], bl[4][2];
            #pragma unroll
            for (int g = 0; g < 2; g++) {
                uint32_t bd = sb + GBHI +
                    (((wn * 2 + g) * 16 + lrow) * 40 + kb + lk) * 2;
                uint32_t r0, r1, r2, r3;
                ldsm4(r0, r1, r2, r3, bd);
                bh[2 * g][0] = r0; bh[2 * g][1] = r2;
                bh[2 * g + 1][0] = r1; bh[2 * g + 1][1] = r3;
                ldsm4(r0, r1, r2, r3, bd + (GBLO - GBHI));
                bl[2 * g][0] = r0; bl[2 * g][1] = r2;
                bl[2 * g + 1][0] = r1; bl[2 * g + 1][1] = r3;
            }
            #pragma unroll
            for (int mf = 0; mf < 4; mf++)
                #pragma unroll
                for (int nf = 0; nf < 4; nf++) {
                    mma16816(c[mf][nf], ah[mf], bh[nf][0], bh[nf][1]);
                    mma16816(c[mf][nf], ah[mf], bl[nf][0], bl[nf][1]);
                    mma16816(c[mf][nf], al[mf], bh[nf][0], bh[nf][1]);
                }
        }
        __syncthreads();
    }

    // epilogue: bias, split-pack, permuted scatter
    const int qr = lane >> 2;
    const int qc = (lane & 3) * 2;
    #pragma unroll
    for (int mf = 0; mf < 4; mf++) {
        #pragma unroll
        for (int rr = 0; rr < 2; rr++) {
            int t = t0 + wm * 64 + mf * 16 + qr + rr * 8;
            int xx = t / 48;
            int toff = t - xx * 48;
            #pragma unroll
            for (int nf = 0; nf < 4; nf++) {
                #pragma unroll
                for (int e = 0; e < 2; e++) {
                    int nn = col0 + wn * 32 + nf * 8 + qc + e;
                    float v = c[mf][nf][rr * 2 + e] + bias[nn];
                    __nv_bfloat16 hv = __float2bfloat16(v);
                    __nv_bfloat16 lv = __float2bfloat16(v - __bfloat162float(hv));
                    uint32_t pv = (uint32_t)__bfloat16_as_ushort(hv) |
                                  ((uint32_t)__bfloat16_as_ushort(lv) << 16);
                    int ee = toff * 1024 + nn;
                    int hh = ee & 15;
                    int ii = ee >> 4;
                    if (mat == 0)      g_q[(hh * TT + ii) * HX + xx] = pv;
                    else if (mat == 1) g_k[(hh * TT + ii) * HX + xx] = pv;
                    else               g_vt[(hh * HX + xx) * TT + ii] = pv;
                }
            }
        }
    }
}

// ---------------------------------------------------------------------------
// Kernel 2: flash attention via mma.sync (register-resident P, split bf16)
// Grid (24 q-tiles, 16 heads), 256 threads (8 warps x 16 query rows).
// ---------------------------------------------------------------------------
#define AQHI 0
#define AQLO 18432
#define AKHI 36864
#define AKLO 55296
#define AVHI 73728
#define AVLO 91136
#define SMEM_A 108544
#define SQK 72    // u16 stride for Q/K rows (144 B)
#define SVT 136   // u16 stride for V^T rows (272 B)

__global__ __launch_bounds__(256, 1)
void attn_mma_kernel(const float* __restrict__ xin,
                     const float* __restrict__ gamma_p,
                     float* __restrict__ out)
{
    extern __shared__ char sm[];
    const uint32_t sb = smem_u32(sm);
    const int tid = threadIdx.x;
    const int lane = tid & 31;
    const int wid = tid >> 5;
    const int h = blockIdx.y;
    const int i0 = blockIdx.x * 128;
    const int lrow = lane & 15;
    const int lk = (lane >> 4) << 3;

    const uint32_t* Qg = g_q + (h * TT + i0) * HX;
    const uint32_t* Kg = g_k + h * TT * HX;
    const uint32_t* Vg = g_vt + h * HX * TT;

    // ---- load Q tile (unpack packed u32 -> hi/lo bf16 smem) ----
    #pragma unroll
    for (int i = 0; i < 16; i++) {
        int idx = tid + i * 256;        // 4096 pairs
        int row = idx >> 5;
        int xp = idx & 31;
        uint2 u = *(const uint2*)(Qg + row * HX + xp * 2);
        uint32_t hi2 = (u.x & 0xffffu) | (u.y << 16);
        uint32_t lo2 = (u.x >> 16) | (u.y & 0xffff0000u);
        int so = (row * SQK + xp * 2) * 2;
        *(uint32_t*)(sm + AQHI + so) = hi2;
        *(uint32_t*)(sm + AQLO + so) = lo2;
    }

    float o[8][4];
    #pragma unroll
    for (int i = 0; i < 8; i++)
        #pragma unroll
        for (int e = 0; e < 4; e++) o[i][e] = 0.f;
    float m0 = -1e30f, m1 = -1e30f, l0 = 0.f, l1 = 0.f;

    for (int j0 = 0; j0 < TT; j0 += 128) {
        // ---- load K tile + V^T tile ----
        #pragma unroll
        for (int i = 0; i < 16; i++) {
            int idx = tid + i * 256;
            int row = idx >> 5;
            int xp = idx & 31;
            uint2 u = *(const uint2*)(Kg + (j0 + row) * HX + xp * 2);
            int so = (row * SQK + xp * 2) * 2;
            *(uint32_t*)(sm + AKHI + so) = (u.x & 0xffffu) | (u.y << 16);
            *(uint32_t*)(sm + AKLO + so) = (u.x >> 16) | (u.y & 0xffff0000u);
        }
        #pragma unroll
        for (int i = 0; i < 16; i++) {
            int idx = tid + i * 256;    // 4096 pairs: 64 rows x 64 j-pairs
            int row = idx >> 6;
            int jp = idx & 63;
            uint2 u = *(const uint2*)(Vg + row * TT + j0 + jp * 2);
            int so = (row * SVT + jp * 2) * 2;
            *(uint32_t*)(sm + AVHI + so) = (u.x & 0xffffu) | (u.y << 16);
            *(uint32_t*)(sm + AVLO + so) = (u.x >> 16) | (u.y & 0xffff0000u);
        }
        __syncthreads();

        // ---- S = Q K^T : warp rows [wid*16, wid*16+16), all 128 cols ----
        float c[16][4];
        #pragma unroll
        for (int i = 0; i < 16; i++)
            #pragma unroll
            for (int e = 0; e < 4; e++) c[i][e] = 0.f;

        #pragma unroll
        for (int ks = 0; ks < 4; ks++) {
            int kb = ks << 4;
            uint32_t ah[4], al[4];
            uint32_t ad = sb + AQHI + ((wid * 16 + lrow) * SQK + kb + lk) * 2;
            ldsm4(ah[0], ah[1], ah[2], ah[3], ad);
            ldsm4(al[0], al[1], al[2], al[3], ad + (AQLO - AQHI));
            #pragma unroll
            for (int ng = 0; ng < 8; ng++) {
                uint32_t bd = sb + AKHI + ((ng * 16 + lrow) * SQK + kb + lk) * 2;
                uint32_t h0, h1, h2, h3, q0, q1, q2, q3;
                ldsm4(h0, h1, h2, h3, bd);
                ldsm4(q0, q1, q2, q3, bd + (AKLO - AKHI));
                mma16816(c[2 * ng],     ah, h0, h2);
                mma16816(c[2 * ng],     ah, q0, q2);
                mma16816(c[2 * ng],     al, h0, h2);
                mma16816(c[2 * ng + 1], ah, h1, h3);
                mma16816(c[2 * ng + 1], ah, q1, q3);
                mma16816(c[2 * ng + 1], al, h1, h3);
            }
        }

        // ---- online softmax (quad-shuffle row reductions) ----
        float mx0 = -1e30f, mx1 = -1e30f;
        #pragma unroll
        for (int nf = 0; nf < 16; nf++) {
            mx0 = fmaxf(mx0, fmaxf(c[nf][0], c[nf][1]));
            mx1 = fmaxf(mx1, fmaxf(c[nf][2], c[nf][3]));
        }
        mx0 = fmaxf(mx0, __shfl_xor_sync(0xffffffffu, mx0, 1));
        mx0 = fmaxf(mx0, __shfl_xor_sync(0xffffffffu, mx0, 2));
        mx1 = fmaxf(mx1, __shfl_xor_sync(0xffffffffu, mx1, 1));
        mx1 = fmaxf(mx1, __shfl_xor_sync(0xffffffffu, mx1, 2));
        float mn0 = fmaxf(m0, mx0), mn1 = fmaxf(m1, mx1);
        float sc0 = __expf(m0 - mn0), sc1 = __expf(m1 - mn1);
        float s0 = 0.f, s1 = 0.f;
        #pragma unroll
        for (int nf = 0; nf < 16; nf++) {
            c[nf][0] = __expf(c[nf][0] - mn0); s0 += c[nf][0];
            c[nf][1] = __expf(c[nf][1] - mn0); s0 += c[nf][1];
            c[nf][2] = __expf(c[nf][2] - mn1); s1 += c[nf][2];
            c[nf][3] = __expf(c[nf][3] - mn1); s1 += c[nf][3];
        }
        s0 += __shfl_xor_sync(0xffffffffu, s0, 1);
        s0 += __shfl_xor_sync(0xffffffffu, s0, 2);
        s1 += __shfl_xor_sync(0xffffffffu, s1, 1);
        s1 += __shfl_xor_sync(0xffffffffu, s1, 2);
        l0 = l0 * sc0 + s0; m0 = mn0;
        l1 = l1 * sc1 + s1; m1 = mn1;
        #pragma unroll
        for (int nf = 0; nf < 8; nf++) {
            o[nf][0] *= sc0; o[nf][1] *= sc0;
            o[nf][2] *= sc1; o[nf][3] *= sc1;
        }

        // ---- O += P V : P packed from S fragments (register pass) ----
        #pragma unroll
        for (int ks2 = 0; ks2 < 8; ks2++) {
            uint32_t ahi[4], alo[4];
            split_pack(c[2 * ks2][0],     c[2 * ks2][1],     ahi[0], alo[0]);
            split_pack(c[2 * ks2][2],     c[2 * ks2][3],     ahi[1], alo[1]);
            split_pack(c[2 * ks2 + 1][0], c[2 * ks2 + 1][1], ahi[2], alo[2]);
            split_pack(c[2 * ks2 + 1][2], c[2 * ks2 + 1][3], ahi[3], alo[3]);
            int kb2 = ks2 << 4;
            #pragma unroll
            for (int ng = 0; ng < 4; ng++) {
                uint32_t bd = sb + AVHI + ((ng * 16 + lrow) * SVT + kb2 + lk) * 2;
                uint32_t h0, h1, h2, h3, q0, q1, q2, q3;
                ldsm4(h0, h1, h2, h3, bd);
                ldsm4(q0, q1, q2, q3, bd + (AVLO - AVHI));
                mma16816(o[2 * ng],     ahi, h0, h2);
                mma16816(o[2 * ng],     ahi, q0, q2);
                mma16816(o[2 * ng],     alo, h0, h2);
                mma16816(o[2 * ng + 1], ahi, h1, h3);
                mma16816(o[2 * ng + 1], ahi, q1, q3);
                mma16816(o[2 * ng + 1], alo, h1, h3);
            }
        }
        __syncthreads();
    }

    // ---- epilogue: out = gamma * O/l + x (permuted) ----
    const float gma = *gamma_p;
    const float inv0 = 1.0f / l0, inv1 = 1.0f / l1;
    const int r0g = i0 + wid * 16 + (lane >> 2);
    const int r1g = r0g + 8;
    #pragma unroll
    for (int nf = 0; nf < 8; nf++) {
        #pragma unroll
        for (int e = 0; e < 2; e++) {
            int x = nf * 8 + (lane & 3) * 2 + e;
            int id0 = r0g * DD + x * 16 + h;
            out[id0] = gma * (o[nf][e] * inv0) + xin[id0];
            int id1 = r1g * DD + x * 16 + h;
            out[id1] = gma * (o[nf][2 + e] * inv1) + xin[id1];
        }
    }
}

// ---------------------------------------------------------------------------
extern "C" void kernel_launch(void* const* d_in, const int* in_sizes, int n_in,
                              void* d_out, int out_size)
{
    const float* xin = (const float*)d_in[0];
    const float* wq  = (const float*)d_in[1];
    const float* bq  = (const float*)d_in[2];
    const float* wk  = (const float*)d_in[3];
    const float* bk  = (const float*)d_in[4];
    const float* wv  = (const float*)d_in[5];
    const float* bv  = (const float*)d_in[6];
    const float* gm  = (const float*)d_in[7];
    float* out = (float*)d_out;

    cudaFuncSetAttribute(qkv_mma_kernel,
                         cudaFuncAttributeMaxDynamicSharedMemorySize, SMEM_G);
    cudaFuncSetAttribute(attn_mma_kernel,
                         cudaFuncAttributeMaxDynamicSharedMemorySize, SMEM_A);

    prep_kernel<<<3072, 256>>>(xin, wq, wk, wv);
    qkv_mma_kernel<<<dim3(24, 24), 256, SMEM_G>>>(bq, bk, bv);
    attn_mma_kernel<<<dim3(24, NH), 256, SMEM_A>>>(xin, gm, out);
}